// round 15
// baseline (speedup 1.0000x reference)
#include <cuda_runtime.h>

// Problem constants (fixed by setup_inputs)
#define N_PTS 2048
#define N_C   1024
#define B_SZ  8
#define BLOCK_THREADS 256
#define PTS_PER_BLOCK 256
#define BLOCKS_PER_BATCH (N_PTS / PTS_PER_BLOCK)   // 8
#define NUM_BLOCKS (B_SZ * BLOCKS_PER_BATCH)       // 64
#define N_TOTAL (B_SZ * N_PTS)                     // 16384
#define NB 512                                     // bins per batch
#define XMIN_F (-4.5f)
#define XRANGE_F (9.0f)

// Output layout (tuple concat): y_diff | x_diff | d_out(B,N,2) | x_n | y_n
#define OFF_YDIFF 0
#define OFF_XDIFF (N_TOTAL)
#define OFF_DOUT  (2 * N_TOTAL)
#define OFF_XN    (4 * N_TOTAL)
#define OFF_YN    (5 * N_TOTAL)

__device__ float2       g_psumv[NUM_BLOCKS];   // per-block (sum, sumsq)
__device__ unsigned int g_cnt = 0;             // monotonic ticket counter (never reset)

typedef unsigned long long ull;

static __device__ __forceinline__ int bin_of(float v) {
    int t = (int)((v - XMIN_F) * ((float)NB / XRANGE_F));
    t = t < 0 ? 0 : t;
    return t > (NB - 1) ? (NB - 1) : t;
}

// Fused: binned NN + derivative + outputs + all-blocks cooperative BN epilogue.
__global__ __launch_bounds__(BLOCK_THREADS) void nn_fused_kernel(
    const float* __restrict__ y, const float* __restrict__ x,
    const float* __restrict__ bn_w, const float* __restrict__ bn_b,
    float* __restrict__ out)
{
    __shared__ float  sx[N_PTS];
    __shared__ float  sy[N_PTS];
    __shared__ float2 bpt[N_PTS];            // (x value, idx bits) in bin order
    __shared__ int    binCnt[NB];
    __shared__ int    binStart[NB + 1];
    __shared__ int    binFill[NB];
    __shared__ float  s_ws[8], s_ws2[8];
    __shared__ float  s_affine[2];

    const int tid   = threadIdx.x;
    const int wid   = tid >> 5;
    const int lane  = tid & 31;
    const int batch = blockIdx.x >> 3;                 // / BLOCKS_PER_BATCH
    const int base  = (blockIdx.x & 7) * PTS_PER_BLOCK;

    const float width = XRANGE_F / (float)NB;

    // ---- Load batch into SMEM, keeping x values in registers ----
    float4 xa, xb;   // this thread's 8 x-values: indices 4*tid..+3, 4*(tid+256)..+3
    {
        const float4* xb4 = (const float4*)(x + batch * N_PTS);
        const float4* yb4 = (const float4*)(y + batch * N_PTS);
        float4* sxv = (float4*)sx;
        float4* syv = (float4*)sy;
        xa = xb4[tid];
        xb = xb4[tid + 256];
        const float4 ya  = yb4[tid];
        const float4 yb_ = yb4[tid + 256];
        sxv[tid]       = xa;
        sxv[tid + 256] = xb;
        syv[tid]       = ya;
        syv[tid + 256] = yb_;
    }
    binCnt[tid]       = 0;
    binCnt[tid + 256] = 0;
    __syncthreads();                                   // B1

    // ---- Histogram from registers (8 points per thread) ----
    atomicAdd(&binCnt[bin_of(xa.x)], 1);
    atomicAdd(&binCnt[bin_of(xa.y)], 1);
    atomicAdd(&binCnt[bin_of(xa.z)], 1);
    atomicAdd(&binCnt[bin_of(xa.w)], 1);
    atomicAdd(&binCnt[bin_of(xb.x)], 1);
    atomicAdd(&binCnt[bin_of(xb.y)], 1);
    atomicAdd(&binCnt[bin_of(xb.z)], 1);
    atomicAdd(&binCnt[bin_of(xb.w)], 1);
    __syncthreads();                                   // B2

    // ---- Exclusive scan over NB=512 bins by warp 0 (16 bins/lane, shuffle scan) ----
    if (wid == 0) {
        const int b0 = lane * (NB / 32);
        int c[NB / 32];
        int run = 0;
        #pragma unroll
        for (int k = 0; k < NB / 32; ++k) {
            c[k] = run;
            run += binCnt[b0 + k];
        }
        int v = run;
        #pragma unroll
        for (int off = 1; off < 32; off <<= 1) {
            int n = __shfl_up_sync(0xffffffffu, v, off);
            if (lane >= off) v += n;
        }
        const int pre = v - run;
        #pragma unroll
        for (int k = 0; k < NB / 32; ++k) {
            const int s = pre + c[k];
            binStart[b0 + k] = s;
            binFill[b0 + k]  = s;
        }
        if (lane == 31) binStart[NB] = pre + run;      // == N_PTS
    }
    __syncthreads();                                   // B3

    // ---- Scatter from registers (counting sort; in-bin order arbitrary) ----
    {
        const int i0 = 4 * tid;
        const int i1 = 4 * (tid + 256);
        int pos;
        pos = atomicAdd(&binFill[bin_of(xa.x)], 1); bpt[pos] = make_float2(xa.x, __int_as_float(i0));
        pos = atomicAdd(&binFill[bin_of(xa.y)], 1); bpt[pos] = make_float2(xa.y, __int_as_float(i0 + 1));
        pos = atomicAdd(&binFill[bin_of(xa.z)], 1); bpt[pos] = make_float2(xa.z, __int_as_float(i0 + 2));
        pos = atomicAdd(&binFill[bin_of(xa.w)], 1); bpt[pos] = make_float2(xa.w, __int_as_float(i0 + 3));
        pos = atomicAdd(&binFill[bin_of(xb.x)], 1); bpt[pos] = make_float2(xb.x, __int_as_float(i1));
        pos = atomicAdd(&binFill[bin_of(xb.y)], 1); bpt[pos] = make_float2(xb.y, __int_as_float(i1 + 1));
        pos = atomicAdd(&binFill[bin_of(xb.z)], 1); bpt[pos] = make_float2(xb.z, __int_as_float(i1 + 2));
        pos = atomicAdd(&binFill[bin_of(xb.w)], 1); bpt[pos] = make_float2(xb.w, __int_as_float(i1 + 3));
    }
    __syncthreads();                                   // B4

    // ---- Per-thread NN search over expanding bin window ----
    const int   p     = base + tid;                    // point index within batch
    const int   limit = (p < N_C) ? (N_C - 1) : p;     // valid candidate: j <= limit
    const float xi    = sx[p];

    // top-2 by exact key = (bits(sqrt_rn(dx*dx)) << 32) | j ; init (+inf, maxidx)
    const ull KEY_INF = ((ull)0x7f800000u << 32) | 0xffffffffu;
    ull k1 = KEY_INF, k2 = KEY_INF;

    const int t0 = bin_of(xi);

    #define SCAN_BIN(T)                                                        \
        {                                                                      \
            const int qe = binStart[(T) + 1];                                  \
            for (int q = binStart[(T)]; q < qe; ++q) {                         \
                const float2 pr = bpt[q];                                      \
                const int j = __float_as_int(pr.y);                            \
                if (j <= limit) {                                              \
                    const float dx   = xi - pr.x;                              \
                    const float dist = __fsqrt_rn(__fmul_rn(dx, dx));          \
                    const ull key = ((ull)__float_as_uint(dist) << 32)         \
                                    | (unsigned int)j;                         \
                    if (key < k1)      { k2 = k1; k1 = key; }                  \
                    else if (key < k2) { k2 = key; }                           \
                }                                                              \
            }                                                                  \
        }

    SCAN_BIN(t0);
    {
        int l = t0 - 1, r = t0 + 1;
        while (true) {
            const float d2v = __uint_as_float((unsigned int)(k2 >> 32)); // +inf until 2 found
            // conservative cushion: covers bin-edge rounding + sqrt rounding ties
            const float thr = d2v + (width * 1e-3f + d2v * 1e-5f);
            const float bl = (l >= 0) ? fmaxf(xi - (XMIN_F + (float)(l + 1) * width), 0.0f)
                                      : __int_as_float(0x7f800000);
            const float br = (r < NB) ? fmaxf((XMIN_F + (float)r * width) - xi, 0.0f)
                                      : __int_as_float(0x7f800000);
            const bool canL = (l >= 0) && (bl <= thr);
            const bool canR = (r < NB) && (br <= thr);
            if (!canL && !canR) break;
            if (canL && (!canR || bl <= br)) { SCAN_BIN(l); --l; }
            else                             { SCAN_BIN(r); ++r; }
        }
    }
    #undef SCAN_BIN

    // ---- Derivative + outputs (raw d2 kept in register; only label stored now) ----
    float d2out;
    int   gidx;
    {
        const int nn = (int)(unsigned int)(k2 & 0xffffffffULL);  // argsort[...,1]
        const float xcl  = sx[nn];
        const float ycl  = sy[nn];
        const float xrep = xi - xcl;
        const float yrep = sy[p] - ycl;
        const float nrm  = __fsqrt_rn(__fmul_rn(xrep, xrep));
        const float d    = __fdiv_rn(yrep, __fadd_rn(2e-6f, nrm));
        const bool  clip = (fabsf(d) > 200.0f);
        d2out = clip ? 0.0f : d;
        const float lab = clip ? 0.0f : 1.0f;

        gidx = batch * N_PTS + p;
        out[OFF_YDIFF + gidx]        = yrep;
        out[OFF_XDIFF + gidx]        = xrep;
        out[OFF_DOUT + 2 * gidx + 1] = lab;
        out[OFF_XN + gidx]           = xcl;
        out[OFF_YN + gidx]           = ycl;
    }

    // ---- Per-warp partial sums (float, fixed shuffle order) -> per-block ----
    {
        float s  = d2out;
        float s2 = d2out * d2out;
        #pragma unroll
        for (int off = 16; off > 0; off >>= 1) {
            s  += __shfl_down_sync(0xffffffffu, s,  off);
            s2 += __shfl_down_sync(0xffffffffu, s2, off);
        }
        if (lane == 0) { s_ws[wid] = s; s_ws2[wid] = s2; }
    }
    __syncthreads();                                   // B5

    // ---- Publish per-block psum; ticket handshake (monotonic, replay-safe) ----
    if (tid == 0) {
        float bs = 0.0f, bs2 = 0.0f;
        #pragma unroll
        for (int w = 0; w < 8; ++w) { bs += s_ws[w]; bs2 += s_ws2[w]; }
        g_psumv[blockIdx.x] = make_float2(bs, bs2);
        __threadfence();
        const unsigned int ticket = atomicAdd(&g_cnt, 1u);
        const unsigned int target = (ticket / NUM_BLOCKS + 1u) * NUM_BLOCKS;
        volatile unsigned int* cp = &g_cnt;
        while (*cp < target) { }
    }
    __syncthreads();                                   // B6 (releases whole block)
    __threadfence();                                   // acquire remote psum writes

    // ---- Every block: reduce 64 psums (fixed order) -> affine ----
    if (wid == 0) {
        const float2 a = g_psumv[lane];
        const float2 b = g_psumv[lane + 32];
        float s  = a.x + b.x;
        float s2 = a.y + b.y;
        #pragma unroll
        for (int off = 16; off > 0; off >>= 1) {
            s  += __shfl_down_sync(0xffffffffu, s,  off);
            s2 += __shfl_down_sync(0xffffffffu, s2, off);
        }
        if (lane == 0) {
            const double n    = (double)N_TOTAL;
            const double mean = (double)s / n;
            const double var  = (double)s2 / n - mean * mean;
            const double invs = 1.0 / sqrt(var + 1e-5);
            const float scale = (float)invs * bn_w[0];
            s_affine[0] = scale;
            s_affine[1] = bn_b[0] - (float)mean * scale;
        }
    }
    __syncthreads();                                   // B7

    // ---- Normalize own d2 from register; single STG, no RMW ----
    out[OFF_DOUT + 2 * gidx] = fmaf(d2out, s_affine[0], s_affine[1]);
}

extern "C" void kernel_launch(void* const* d_in, const int* in_sizes, int n_in,
                              void* d_out, int out_size) {
    const float* y    = (const float*)d_in[0];
    const float* x    = (const float*)d_in[1];
    const float* bn_w = (const float*)d_in[2];
    const float* bn_b = (const float*)d_in[3];
    float* out = (float*)d_out;

    nn_fused_kernel<<<NUM_BLOCKS, BLOCK_THREADS>>>(y, x, bn_w, bn_b, out);
}